// round 1
// baseline (speedup 1.0000x reference)
#include <cuda_runtime.h>
#include <math.h>
#include <stdint.h>

#define B_  4
#define LQ_ 5440
#define D_  256
#define H_  8
#define HD_ 32
#define FF_ 1024
#define NL_ 6
#define MROWS (B_*LQ_)   // 21760

// ---------------- scratch (device globals; no allocation) ----------------
__device__ float g_pos [MROWS*D_];
__device__ float g_out [MROWS*D_];
__device__ float g_v   [MROWS*D_];
__device__ float g_off [MROWS*D_];
__device__ float g_attn[MROWS*128];
__device__ float g_def [MROWS*D_];
__device__ float g_tmp [MROWS*D_];
__device__ float g_ffn [MROWS*FF_];
__device__ float g_ref [LQ_*2];

// ---------------- flatten + transpose: [B,D,HW] -> rows [base..base+HW) of [B,LQ,D]
__global__ void flatten_kernel(const float* __restrict__ src,
                               const float* __restrict__ lvl,   // level embed [D] or null
                               float* __restrict__ dst,
                               int HW, int base)
{
    __shared__ float tile[32][33];
    int b  = blockIdx.z;
    int tx = threadIdx.x, ty = threadIdx.y;
    int hw0 = blockIdx.x * 32;
    int d0  = blockIdx.y * 32;
    const float* sp = src + ((size_t)b * D_) * HW;
    #pragma unroll
    for (int j = 0; j < 32; j += 8) {
        tile[ty + j][tx] = sp[(size_t)(d0 + ty + j) * HW + hw0 + tx];
    }
    __syncthreads();
    float add = (lvl != nullptr) ? lvl[d0 + tx] : 0.0f;
    #pragma unroll
    for (int j = 0; j < 32; j += 8) {
        int hw = hw0 + ty + j;
        dst[((size_t)b * LQ_ + base + hw) * D_ + d0 + tx] = tile[tx][ty + j] + add;
    }
}

// ---------------- reference points ----------------
__global__ void ref_kernel(float* __restrict__ ref)
{
    int q = blockIdx.x * 256 + threadIdx.x;
    if (q >= LQ_) return;
    int base, W;
    if      (q < 4096) { base = 0;    W = 64; }
    else if (q < 5120) { base = 4096; W = 32; }
    else if (q < 5376) { base = 5120; W = 16; }
    else               { base = 5376; W = 8;  }
    int idx = q - base;
    int ry = idx / W, rx = idx % W;
    ref[q * 2 + 0] = (rx + 0.5f) / (float)W;
    ref[q * 2 + 1] = (ry + 0.5f) / (float)W;   // square levels: H==W
}

// ---------------- GEMM: C[M,N] = (A (+A2)) @ W + bias, optional relu ----------------
// BM=64 BN=64 BK=16, 256 threads, 4x4 per thread. M divisible by 64, N by 64 (or 128 ok), K by 16.
template<int DO_RELU, int HAS_ADD>
__global__ void __launch_bounds__(256) gemm_kernel(
    const float* __restrict__ A, const float* __restrict__ A2,
    const float* __restrict__ W, const float* __restrict__ bias,
    float* __restrict__ C, int N, int K)
{
    const int BM = 64, BN = 64, BK = 16;
    __shared__ float As[BK][BM + 1];
    __shared__ float Bs[BK][BN];

    int tid = threadIdx.x;
    int bm = blockIdx.y * BM;
    int bn = blockIdx.x * BN;
    int ty = tid / 16, tx = tid % 16;

    float acc[4][4] = {};

    int a_m = tid / 4;          // 0..63
    int a_k = (tid % 4) * 4;    // 0,4,8,12
    int b_k = tid / 16;         // 0..15
    int b_n = (tid % 16) * 4;   // 0..60

    const float* Aptr  = A  + (size_t)(bm + a_m) * K + a_k;
    const float* A2ptr = HAS_ADD ? (A2 + (size_t)(bm + a_m) * K + a_k) : nullptr;
    const float* Wptr  = W  + (size_t)b_k * N + bn + b_n;

    for (int k0 = 0; k0 < K; k0 += BK) {
        float4 av = *(const float4*)(Aptr + k0);
        if (HAS_ADD) {
            float4 a2 = *(const float4*)(A2ptr + k0);
            av.x += a2.x; av.y += a2.y; av.z += a2.z; av.w += a2.w;
        }
        As[a_k + 0][a_m] = av.x;
        As[a_k + 1][a_m] = av.y;
        As[a_k + 2][a_m] = av.z;
        As[a_k + 3][a_m] = av.w;
        float4 bv = *(const float4*)(Wptr + (size_t)k0 * N);
        *(float4*)&Bs[b_k][b_n] = bv;
        __syncthreads();

        #pragma unroll
        for (int k = 0; k < BK; k++) {
            float ar[4], br[4];
            #pragma unroll
            for (int i = 0; i < 4; i++) ar[i] = As[k][ty * 4 + i];
            #pragma unroll
            for (int j = 0; j < 4; j++) br[j] = Bs[k][tx * 4 + j];
            #pragma unroll
            for (int i = 0; i < 4; i++)
                #pragma unroll
                for (int j = 0; j < 4; j++)
                    acc[i][j] = fmaf(ar[i], br[j], acc[i][j]);
        }
        __syncthreads();
    }

    #pragma unroll
    for (int i = 0; i < 4; i++) {
        int m = bm + ty * 4 + i;
        int n = bn + tx * 4;
        float4 o;
        o.x = acc[i][0] + bias[n + 0];
        o.y = acc[i][1] + bias[n + 1];
        o.z = acc[i][2] + bias[n + 2];
        o.w = acc[i][3] + bias[n + 3];
        if (DO_RELU) {
            o.x = fmaxf(o.x, 0.f); o.y = fmaxf(o.y, 0.f);
            o.z = fmaxf(o.z, 0.f); o.w = fmaxf(o.w, 0.f);
        }
        *(float4*)(C + (size_t)m * N + n) = o;
    }
}

// ---------------- LayerNorm with fused residual: out = LN(x + r) ----------------
__global__ void __launch_bounds__(256) ln_kernel(
    const float* __restrict__ x, const float* __restrict__ r,
    const float* __restrict__ g, const float* __restrict__ bta,
    float* __restrict__ out)
{
    int row = blockIdx.x;
    int d = threadIdx.x;
    size_t idx = (size_t)row * D_ + d;
    float v = x[idx] + r[idx];

    __shared__ float sh[8];
    float s = v;
    #pragma unroll
    for (int o = 16; o; o >>= 1) s += __shfl_xor_sync(0xffffffffu, s, o);
    if ((d & 31) == 0) sh[d >> 5] = s;
    __syncthreads();
    float mean = (sh[0]+sh[1]+sh[2]+sh[3]+sh[4]+sh[5]+sh[6]+sh[7]) * (1.0f / D_);
    __syncthreads();

    float c = v - mean;
    float s2 = c * c;
    #pragma unroll
    for (int o = 16; o; o >>= 1) s2 += __shfl_xor_sync(0xffffffffu, s2, o);
    if ((d & 31) == 0) sh[d >> 5] = s2;
    __syncthreads();
    float var = (sh[0]+sh[1]+sh[2]+sh[3]+sh[4]+sh[5]+sh[6]+sh[7]) * (1.0f / D_);

    out[idx] = c * rsqrtf(var + 1e-5f) * g[d] + bta[d];
}

// ---------------- deformable attention (one warp per (b,q,h), lane = channel) ----------
__global__ void __launch_bounds__(256) deform_kernel(
    const float* __restrict__ v,      // [B,LQ,H,HD]
    const float* __restrict__ off,    // [B,LQ,H,L,P,2] = [.,256]
    const float* __restrict__ logits, // [B,LQ,H,16]   = [.,128]
    const float* __restrict__ ref,    // [LQ,2]
    float* __restrict__ out)          // [B,LQ,D]
{
    const int dims [4] = {64, 32, 16, 8};
    const int bases[4] = {0, 4096, 5120, 5376};

    int bq   = blockIdx.x;              // b*LQ + q
    int h    = threadIdx.x >> 5;
    int lane = threadIdx.x & 31;
    int b = bq / LQ_;
    int q = bq % LQ_;

    // softmax over 16 logits (lanes 0..15 active)
    const float* lg = logits + (size_t)bq * 128 + h * 16;
    float xv = (lane < 16) ? lg[lane] : -1e30f;
    float m = xv;
    #pragma unroll
    for (int o = 8; o; o >>= 1) m = fmaxf(m, __shfl_xor_sync(0xffffffffu, m, o));
    float e = (lane < 16) ? __expf(xv - m) : 0.0f;
    float s = e;
    #pragma unroll
    for (int o = 8; o; o >>= 1) s += __shfl_xor_sync(0xffffffffu, s, o);
    float aw = e / s;

    // 32 offset floats for this (bq,h): lane-parallel load, fetch via shfl
    float offv = off[(size_t)bq * 256 + h * 32 + lane];
    float refx = ref[q * 2 + 0];
    float refy = ref[q * 2 + 1];

    const float* vb = v + (size_t)b * LQ_ * 256 + h * HD_ + lane;

    float acc = 0.0f;
    #pragma unroll
    for (int l = 0; l < 4; l++) {
        const int Wl = dims[l];
        const int base = bases[l];
        const float Wf = (float)Wl;
        #pragma unroll
        for (int p = 0; p < 4; p++) {
            int pt = l * 4 + p;
            float ax = __shfl_sync(0xffffffffu, offv, pt * 2 + 0);
            float ay = __shfl_sync(0xffffffffu, offv, pt * 2 + 1);
            float a  = __shfl_sync(0xffffffffu, aw, pt);
            float xf = refx * Wf + ax - 0.5f;
            float yf = refy * Wf + ay - 0.5f;
            float x0f = floorf(xf), y0f = floorf(yf);
            float wx = xf - x0f,   wy = yf - y0f;
            int x0 = (int)x0f, y0 = (int)y0f;
            int x1 = x0 + 1,   y1 = y0 + 1;

            float w00 = (1.f - wy) * (1.f - wx);
            float w01 = (1.f - wy) * wx;
            float w10 = wy * (1.f - wx);
            float w11 = wy * wx;

            if (y0 >= 0 && y0 < Wl) {
                if (x0 >= 0 && x0 < Wl)
                    acc = fmaf(a * w00, vb[(size_t)(base + y0 * Wl + x0) * 256], acc);
                if (x1 >= 0 && x1 < Wl)
                    acc = fmaf(a * w01, vb[(size_t)(base + y0 * Wl + x1) * 256], acc);
            }
            if (y1 >= 0 && y1 < Wl) {
                if (x0 >= 0 && x0 < Wl)
                    acc = fmaf(a * w10, vb[(size_t)(base + y1 * Wl + x0) * 256], acc);
                if (x1 >= 0 && x1 < Wl)
                    acc = fmaf(a * w11, vb[(size_t)(base + y1 * Wl + x1) * 256], acc);
            }
        }
    }
    out[(size_t)bq * 256 + h * HD_ + lane] = acc;
}

// ---------------- host orchestration ----------------
static float* sym_ptr(const void* sym)
{
    void* p = nullptr;
    cudaGetSymbolAddress(&p, sym);
    return (float*)p;
}

extern "C" void kernel_launch(void* const* d_in, const int* in_sizes, int n_in,
                              void* d_out, int out_size)
{
    // Detect input ordering: interleaved (src0,pos0,src1,pos1,...) vs grouped.
    bool interleaved = (in_sizes[1] == in_sizes[0]);
    const float* srcs[4];
    const float* poss[4];
    for (int l = 0; l < 4; l++) {
        srcs[l] = (const float*)d_in[interleaved ? 2 * l     : l];
        poss[l] = (const float*)d_in[interleaved ? 2 * l + 1 : 4 + l];
    }
    const float* level_embed = (const float*)d_in[8];
    const float* W_off  = (const float*)d_in[9];
    const float* b_off  = (const float*)d_in[10];
    const float* W_attn = (const float*)d_in[11];
    const float* b_attn = (const float*)d_in[12];
    const float* W_v    = (const float*)d_in[13];
    const float* b_v    = (const float*)d_in[14];
    const float* W_o    = (const float*)d_in[15];
    const float* b_o    = (const float*)d_in[16];
    const float* ln1_g  = (const float*)d_in[17];
    const float* ln1_b  = (const float*)d_in[18];
    const float* W_fc1  = (const float*)d_in[19];
    const float* b_fc1  = (const float*)d_in[20];
    const float* W_fc2  = (const float*)d_in[21];
    const float* b_fc2  = (const float*)d_in[22];
    const float* ln2_g  = (const float*)d_in[23];
    const float* ln2_b  = (const float*)d_in[24];

    float* pos  = sym_ptr(g_pos);
    float* out  = sym_ptr(g_out);
    float* vv   = sym_ptr(g_v);
    float* offb = sym_ptr(g_off);
    float* attn = sym_ptr(g_attn);
    float* defo = sym_ptr(g_def);
    float* tmp  = sym_ptr(g_tmp);
    float* ffn  = sym_ptr(g_ffn);
    float* ref  = sym_ptr(g_ref);

    const int HWs[4]   = {4096, 1024, 256, 64};
    const int bases[4] = {0, 4096, 5120, 5376};

    dim3 tb(32, 8);
    for (int l = 0; l < 4; l++) {
        dim3 gr(HWs[l] / 32, D_ / 32, B_);
        flatten_kernel<<<gr, tb>>>(srcs[l], nullptr, out, HWs[l], bases[l]);
        flatten_kernel<<<gr, tb>>>(poss[l], level_embed + l * D_, pos, HWs[l], bases[l]);
    }
    ref_kernel<<<(LQ_ + 255) / 256, 256>>>(ref);

    const int MB = MROWS / 64; // 340
    for (int i = 0; i < NL_; i++) {
        const float* Wv  = W_v    + (size_t)i * D_ * D_;
        const float* bv  = b_v    + (size_t)i * D_;
        const float* Wof = W_off  + (size_t)i * D_ * 256;
        const float* bof = b_off  + (size_t)i * 256;
        const float* Wa  = W_attn + (size_t)i * D_ * 128;
        const float* ba  = b_attn + (size_t)i * 128;
        const float* Wo  = W_o    + (size_t)i * D_ * D_;
        const float* bo  = b_o    + (size_t)i * D_;
        const float* Wf1 = W_fc1  + (size_t)i * D_ * FF_;
        const float* bf1 = b_fc1  + (size_t)i * FF_;
        const float* Wf2 = W_fc2  + (size_t)i * FF_ * D_;
        const float* bf2 = b_fc2  + (size_t)i * D_;

        gemm_kernel<0,0><<<dim3(D_/64,  MB), 256>>>(out, nullptr, Wv,  bv,  vv,   D_,  D_);
        gemm_kernel<0,1><<<dim3(256/64, MB), 256>>>(out, pos,     Wof, bof, offb, 256, D_);
        gemm_kernel<0,1><<<dim3(128/64, MB), 256>>>(out, pos,     Wa,  ba,  attn, 128, D_);

        deform_kernel<<<MROWS, 256>>>(vv, offb, attn, ref, defo);

        gemm_kernel<0,0><<<dim3(D_/64, MB), 256>>>(defo, nullptr, Wo, bo, tmp, D_, D_);
        ln_kernel<<<MROWS, 256>>>(out, tmp, ln1_g + i * D_, ln1_b + i * D_, out);

        gemm_kernel<1,0><<<dim3(FF_/64, MB), 256>>>(out, nullptr, Wf1, bf1, ffn, FF_, D_);
        gemm_kernel<0,0><<<dim3(D_/64,  MB), 256>>>(ffn, nullptr, Wf2, bf2, tmp, D_, FF_);

        float* lnout = (i == NL_ - 1) ? (float*)d_out : out;
        ln_kernel<<<MROWS, 256>>>(out, tmp, ln2_g + i * D_, ln2_b + i * D_, lnout);
    }
}